// round 9
// baseline (speedup 1.0000x reference)
#include <cuda_runtime.h>
#include <math.h>

#define BB 2
#define CC 16
#define NV (64*64*64)            // 262144
#define HDIM 128
#define WDIM 128
#define PPN 3

// Scratch (static device arrays; allocation-free per harness rules).
__device__ float g_xi[BB*CC*NV];      // 33.5 MB : xi, later h
__device__ float g_om[BB*9*NV];       // 18.9 MB : 6 offset + 3 mask channels
__device__ float g_xsum[BB*CC*NV];    // 33.5 MB : deformable-attention sum

// Packed dual-fp32 FMA (sm_100+): d = a*b + c elementwise on two fp32 lanes.
__device__ __forceinline__ unsigned long long fma2(unsigned long long a,
                                                   unsigned long long b,
                                                   unsigned long long c) {
    unsigned long long d;
    asm("fma.rn.f32x2 %0, %1, %2, %3;" : "=l"(d) : "l"(a), "l"(b), "l"(c));
    return d;
}

// Two co-pairs fetched with one LDS.128 (16B-aligned in s_w).
struct __align__(16) WPair { unsigned long long a, b; };

// Closed-form _xray_coords (theta=pi, phi=0, gamma=pi/2, sdr=200, del=2,
// spacing=1, D=H=W=64, Hd=Wd=128); double then cast matches numpy f64->f32.
__device__ __forceinline__ void xray_coords(int d, int h, int w, float& py, float& px) {
    double wgt = 400.0 / (double)(d + 168);
    py = (float)(((wgt * (double)(h - 32) + 32.0) + 95.0) * 0.5);
    px = (float)(((wgt * (double)(w - 32) + 32.0) + 95.0) * 0.5);
}

// ---------------------------------------------------------------------------
// Kernel 1: xi = bilinear sample of Xray at Xrc (coords interior, no clamps).
// ---------------------------------------------------------------------------
__global__ void xi_kernel(const float* __restrict__ Xray, float* __restrict__ xi) {
    int idx = blockIdx.x * blockDim.x + threadIdx.x;
    if (idx >= BB * NV) return;
    int w = idx & 63, h = (idx >> 6) & 63, d = (idx >> 12) & 63, b = idx >> 18;
    int vox = idx & (NV - 1);

    float py, px;
    xray_coords(d, h, w, py, px);
    float fy = floorf(py), fx = floorf(px);
    int y0 = (int)fy, x0 = (int)fx;
    float ay = py - fy, ax = px - fx;
    float wlt = (1.f - ay) * (1.f - ax);
    float wrb = ay * ax;
    float wrt = (1.f - ay) * ax;
    float wlb = ay * (1.f - ax);

    const float* Xb = Xray + (size_t)b * CC * HDIM * WDIM;
    int i00 = y0 * WDIM + x0;
#pragma unroll
    for (int c = 0; c < CC; c++) {
        const float* p = Xb + (size_t)c * HDIM * WDIM;
        float v = wlt * p[i00] + wrt * p[i00 + 1]
                + wlb * p[i00 + WDIM] + wrb * p[i00 + WDIM + 1];
        xi[((size_t)(b * CC + c)) * NV + vox] = v;
    }
}

// ---------------------------------------------------------------------------
// 3x3x3 conv, pad 1, f32x2-packed over co-pairs, 4-voxel x-blocking,
// software-pipelined over cin (double-buffered SMEM, 1 barrier/cin).
// Weights fetched TWO co-pairs at a time via LDS.128 (WPair); MODE2 weight
// storage padded to 12 floats/tap so WPair loads stay 16B-aligned.
// 128 thr; out tile 16x8x4; halo 18x10x6 duplicated (v,v), row stride 19.
// MODE 0: +bias. MODE 1: +BN+leaky. MODE 2: fused offset(6)+mask(3).
// ---------------------------------------------------------------------------
template<int CIN, int COUTP, int MODE>
__global__ __launch_bounds__(128)
void conv3_f2(const float* __restrict__ inA, const float* __restrict__ inB,
              const float* __restrict__ WtA, const float* __restrict__ bAv,
              const float* __restrict__ WtB, const float* __restrict__ bBv,
              float* __restrict__ out,
              const float* __restrict__ gamma, const float* __restrict__ beta,
              const float* __restrict__ mean, const float* __restrict__ var) {
    constexpr int CSTORE = (MODE == 2) ? 12 : COUTP;   // padded storage width
    constexpr int NCP = (MODE == 2) ? 5 : COUTP / 2;   // computed co-pairs
    constexpr int N128 = NCP / 2;                      // full WPair loads/tap
    constexpr int REM  = NCP & 1;                      // trailing u64 load
    constexpr int WPT  = CSTORE / 4;                   // WPairs per tap
    constexpr int TILE_N = 1080;                       // 6*10*18 halo voxels
    constexpr int NT = 9;                              // ceil(1080/128)
    constexpr int WN = 27 * CSTORE;
    constexpr int NW = (WN + 127) / 128;
    __shared__ __align__(16) float2 s_t[2][6 * 10 * 19];
    __shared__ __align__(16) float  s_w[2][WN];

    int bi = blockIdx.x;
    int xt = bi & 3, yt = (bi >> 2) & 7, zt = (bi >> 5) & 15, b = bi >> 9;
    int tx = xt * 16, ty = yt * 8, tz = zt * 4;
    int tid = threadIdx.x;
    int lx4 = tid & 3, ly = (tid >> 2) & 7, lz = tid >> 5;

    float tr[NT];   // in-flight tile values for next cin
    float wr[NW];   // in-flight weights for next cin

    auto load_regs = [&](int cin) {
        const float* src = (CIN == 32 && cin >= 16)
            ? inB + ((size_t)(b * 16 + (cin - 16))) * NV
            : inA + ((size_t)(b * 16 + cin)) * NV;
#pragma unroll
        for (int k = 0; k < NT; k++) {
            int i = tid + k * 128;
            float v = 0.f;
            if (i < TILE_N) {
                int z = i / 180, r = i - z * 180, y = r / 18, x = r - y * 18;
                int gz = tz + z - 1, gy = ty + y - 1, gx = tx + x - 1;
                if ((unsigned)gz < 64u && (unsigned)gy < 64u && (unsigned)gx < 64u)
                    v = src[(gz << 12) + (gy << 6) + gx];
            }
            tr[k] = v;
        }
#pragma unroll
        for (int k = 0; k < NW; k++) {
            int j = tid + k * 128;
            float wv = 0.f;
            if (j < WN) {
                int tap = j / CSTORE, co = j - tap * CSTORE;
                if (MODE == 2) {
                    wv = (co < 6) ? WtA[(size_t)co * (CIN * 27) + cin * 27 + tap]
                       : (co < 9) ? WtB[(size_t)(co - 6) * (CIN * 27) + cin * 27 + tap]
                       : 0.f;                      // padded channels 9..11
                } else {
                    wv = WtA[(size_t)co * (CIN * 27) + cin * 27 + tap];
                }
            }
            wr[k] = wv;
        }
    };
    auto sts = [&](int p) {
#pragma unroll
        for (int k = 0; k < NT; k++) {
            int i = tid + k * 128;
            if (i < TILE_N) {
                int z = i / 180, r = i - z * 180, y = r / 18, x = r - y * 18;
                s_t[p][(z * 10 + y) * 19 + x] = make_float2(tr[k], tr[k]);
            }
        }
#pragma unroll
        for (int k = 0; k < NW; k++) {
            int j = tid + k * 128;
            if (j < WN) s_w[p][j] = wr[k];
        }
    };

    unsigned long long acc[NCP][4];
#pragma unroll
    for (int cp = 0; cp < NCP; cp++)
#pragma unroll
        for (int x = 0; x < 4; x++) acc[cp][x] = 0ull;

    load_regs(0);
    sts(0);
    __syncthreads();

    for (int cin = 0; cin < CIN; cin++) {
        int p = cin & 1;
        if (cin + 1 < CIN) load_regs(cin + 1);   // issue LDGs early

        const WPair* wp =
            reinterpret_cast<const WPair*>(s_w[p]);
        const unsigned long long* w64 =
            reinterpret_cast<const unsigned long long*>(s_w[p]);
        const float2* tp = s_t[p];
#pragma unroll
        for (int kd = 0; kd < 3; kd++)
#pragma unroll
            for (int kh = 0; kh < 3; kh++) {
                const unsigned long long* row =
                    reinterpret_cast<const unsigned long long*>(tp)
                    + ((lz + kd) * 10 + (ly + kh)) * 19 + lx4 * 4;
                unsigned long long vp[6];
#pragma unroll
                for (int j = 0; j < 6; j++) vp[j] = row[j];
#pragma unroll
                for (int kw = 0; kw < 3; kw++) {
                    int tap = kd * 9 + kh * 3 + kw;
#pragma unroll
                    for (int q = 0; q < N128; q++) {
                        WPair w = wp[tap * WPT + q];     // LDS.128: 2 co-pairs
                        int c0 = 2 * q, c1 = 2 * q + 1;
                        acc[c0][0] = fma2(vp[kw + 0], w.a, acc[c0][0]);
                        acc[c0][1] = fma2(vp[kw + 1], w.a, acc[c0][1]);
                        acc[c0][2] = fma2(vp[kw + 2], w.a, acc[c0][2]);
                        acc[c0][3] = fma2(vp[kw + 3], w.a, acc[c0][3]);
                        acc[c1][0] = fma2(vp[kw + 0], w.b, acc[c1][0]);
                        acc[c1][1] = fma2(vp[kw + 1], w.b, acc[c1][1]);
                        acc[c1][2] = fma2(vp[kw + 2], w.b, acc[c1][2]);
                        acc[c1][3] = fma2(vp[kw + 3], w.b, acc[c1][3]);
                    }
                    if (REM) {
                        unsigned long long w = w64[tap * (CSTORE / 2) + (NCP - 1)];
                        acc[NCP-1][0] = fma2(vp[kw + 0], w, acc[NCP-1][0]);
                        acc[NCP-1][1] = fma2(vp[kw + 1], w, acc[NCP-1][1]);
                        acc[NCP-1][2] = fma2(vp[kw + 2], w, acc[NCP-1][2]);
                        acc[NCP-1][3] = fma2(vp[kw + 3], w, acc[NCP-1][3]);
                    }
                }
            }

        if (cin + 1 < CIN) sts(1 - p);           // STS after compute: LDG hidden
        __syncthreads();
    }

    int gx = tx + lx4 * 4, gy = ty + ly, gz = tz + lz;
    size_t vox = (size_t)((gz << 12) + (gy << 6) + gx);
    constexpr int OST = (MODE == 2) ? 9 : 16;
#pragma unroll
    for (int cp = 0; cp < NCP; cp++) {
        float2 a0 = *reinterpret_cast<float2*>(&acc[cp][0]);
        float2 a1 = *reinterpret_cast<float2*>(&acc[cp][1]);
        float2 a2 = *reinterpret_cast<float2*>(&acc[cp][2]);
        float2 a3 = *reinterpret_cast<float2*>(&acc[cp][3]);
#pragma unroll
        for (int half = 0; half < 2; half++) {
            int co = 2 * cp + half;
            if (MODE == 2 && co >= 9) continue;
            float4 o;
            o.x = half ? a0.y : a0.x;
            o.y = half ? a1.y : a1.x;
            o.z = half ? a2.y : a2.x;
            o.w = half ? a3.y : a3.x;
            float bia = (MODE == 2) ? ((co < 6) ? bAv[co] : bBv[co - 6]) : bAv[co];
            o.x += bia; o.y += bia; o.z += bia; o.w += bia;
            if (MODE == 1) {
                float sc = rsqrtf(var[co] + 1e-5f) * gamma[co];
                float mu = mean[co], be = beta[co];
                o.x = (o.x - mu) * sc + be; o.x = (o.x >= 0.f) ? o.x : 0.2f * o.x;
                o.y = (o.y - mu) * sc + be; o.y = (o.y >= 0.f) ? o.y : 0.2f * o.y;
                o.z = (o.z - mu) * sc + be; o.z = (o.z >= 0.f) ? o.z : 0.2f * o.z;
                o.w = (o.w - mu) * sc + be; o.w = (o.w >= 0.f) ? o.w : 0.2f * o.w;
            }
            *reinterpret_cast<float4*>(&out[((size_t)(b * OST + co)) * NV + vox]) = o;
        }
    }
}

// ---------------------------------------------------------------------------
// Kernel 3: softmax(mask) + deformable bilinear gather on the zero-padded
// 130x130 Xray; writes Xsum and the p_coor output (exact reference formulas).
// ---------------------------------------------------------------------------
__global__ void deform_kernel(const float* __restrict__ Xray, const float* __restrict__ om,
                              float* __restrict__ xsum, float* __restrict__ pcoor) {
    int idx = blockIdx.x * blockDim.x + threadIdx.x;
    if (idx >= BB * NV) return;
    int w = idx & 63, h = (idx >> 6) & 63, d = (idx >> 12) & 63, b = idx >> 18;
    int vox = idx & (NV - 1);

    const float* omb = om + (size_t)b * 9 * NV;
    float off[6];
#pragma unroll
    for (int j = 0; j < 6; j++) off[j] = omb[(size_t)j * NV + vox];
    float m0 = omb[(size_t)6 * NV + vox];
    float m1 = omb[(size_t)7 * NV + vox];
    float m2 = omb[(size_t)8 * NV + vox];
    float mx = fmaxf(m0, fmaxf(m1, m2));
    float e0 = expf(m0 - mx), e1 = expf(m1 - mx), e2 = expf(m2 - mx);
    float inv = 1.f / (e0 + e1 + e2);
    float mm[3] = { e0 * inv, e1 * inv, e2 * inv };

    float py0, px0;
    xray_coords(d, h, w, py0, px0);

    int   idx4[PPN][4];
    float wgt4[PPN][4];
#pragma unroll
    for (int p = 0; p < PPN; p++) {
        float py = fminf(fmaxf(off[p] + py0 + 1.f, 0.f), (float)(HDIM + 1));
        float px = fminf(fmaxf(off[PPN + p] + px0 + 1.f, 0.f), (float)(WDIM + 1));
        pcoor[(size_t)idx * 6 + p]        = py;
        pcoor[(size_t)idx * 6 + PPN + p]  = px;

        int fy = (int)floorf(py), fx = (int)floorf(px);
        int y0 = min(fy, HDIM + 1),     y1 = min(fy + 1, HDIM + 1);
        int x0 = min(fx, WDIM + 1),     x1 = min(fx + 1, WDIM + 1);
        float wy0 = 1.f + (float)y0 - py;
        float wy1 = 1.f - ((float)y1 - py);
        float wx0 = 1.f + (float)x0 - px;
        float wx1 = 1.f - ((float)x1 - px);

        int e00 = (y0 >= 1 && y0 <= HDIM && x0 >= 1 && x0 <= WDIM) ? ((y0 - 1) * WDIM + (x0 - 1)) : -1;
        int e11 = (y1 >= 1 && y1 <= HDIM && x1 >= 1 && x1 <= WDIM) ? ((y1 - 1) * WDIM + (x1 - 1)) : -1;
        int e01 = (y0 >= 1 && y0 <= HDIM && x1 >= 1 && x1 <= WDIM) ? ((y0 - 1) * WDIM + (x1 - 1)) : -1;
        int e10 = (y1 >= 1 && y1 <= HDIM && x0 >= 1 && x0 <= WDIM) ? ((y1 - 1) * WDIM + (x0 - 1)) : -1;
        idx4[p][0] = e00; idx4[p][1] = e11; idx4[p][2] = e01; idx4[p][3] = e10;
        wgt4[p][0] = mm[p] * wy0 * wx0;
        wgt4[p][1] = mm[p] * wy1 * wx1;
        wgt4[p][2] = mm[p] * wy0 * wx1;
        wgt4[p][3] = mm[p] * wy1 * wx0;
    }

    const float* Xb = Xray + (size_t)b * CC * HDIM * WDIM;
#pragma unroll
    for (int c = 0; c < CC; c++) {
        const float* pl = Xb + (size_t)c * HDIM * WDIM;
        float s = 0.f;
#pragma unroll
        for (int p = 0; p < PPN; p++)
#pragma unroll
            for (int q = 0; q < 4; q++) {
                int i4 = idx4[p][q];
                float v = (i4 >= 0) ? pl[i4] : 0.f;
                s += wgt4[p][q] * v;
            }
        xsum[((size_t)(b * CC + c)) * NV + vox] = s;
    }
}

// ---------------------------------------------------------------------------
// Launch. Output layout: [ conv2 out (B,C,D,H,W) | p_coor (B,D,H,W,6) ].
// ---------------------------------------------------------------------------
extern "C" void kernel_launch(void* const* d_in, const int* in_sizes, int n_in,
                              void* d_out, int out_size) {
    const float* CT    = (const float*)d_in[0];
    const float* Xray  = (const float*)d_in[1];
    const float* pW    = (const float*)d_in[2];
    const float* pb    = (const float*)d_in[3];
    const float* mW    = (const float*)d_in[4];
    const float* mb    = (const float*)d_in[5];
    const float* w1    = (const float*)d_in[6];
    const float* b1    = (const float*)d_in[7];
    const float* w2    = (const float*)d_in[8];
    const float* b2    = (const float*)d_in[9];
    const float* gamma = (const float*)d_in[10];
    const float* beta  = (const float*)d_in[11];
    const float* mean  = (const float*)d_in[12];
    const float* var   = (const float*)d_in[13];

    float* xi_p; cudaGetSymbolAddress((void**)&xi_p, g_xi);
    float* om_p; cudaGetSymbolAddress((void**)&om_p, g_om);
    float* xs_p; cudaGetSymbolAddress((void**)&xs_p, g_xsum);

    float* out   = (float*)d_out;
    float* pcoor = out + (size_t)BB * CC * NV;   // 8388608

    const int nthr = 256;
    const int nblk = (BB * NV + nthr - 1) / nthr;   // 2048
    const int cblk = 4 * 8 * 16 * BB;               // 1024 conv tiles

    // 1) xi = bilerp_single(Xrc, Xray)
    xi_kernel<<<nblk, nthr>>>(Xray, xi_p);
    // 2) fused offset(6)+mask(3) conv over [CT | xi]  (padded weight storage)
    conv3_f2<32, 10, 2><<<cblk, 128>>>(CT, xi_p, pW, pb, mW, mb, om_p,
                                       nullptr, nullptr, nullptr, nullptr);
    // 3) softmax + deformable gather -> Xsum, p_coor
    deform_kernel<<<nblk, nthr>>>(Xray, om_p, xs_p, pcoor);
    // 4) conv1 over [CT | Xsum] + BN + leaky -> h (reuses g_xi)
    conv3_f2<32, 16, 1><<<cblk, 128>>>(CT, xs_p, w1, b1, nullptr, nullptr, xi_p,
                                       gamma, beta, mean, var);
    // 5) conv2 (16->16) -> final output
    conv3_f2<16, 16, 0><<<cblk, 128>>>(xi_p, nullptr, w2, b2, nullptr, nullptr, out,
                                       nullptr, nullptr, nullptr, nullptr);
}